// round 2
// baseline (speedup 1.0000x reference)
#include <cuda_runtime.h>
#include <math_constants.h>

#define TOKENS  8192
#define HIDDEN  6144
#define EXPERTS 768
#define TOPK    12
#define RSCALE  2.5f

// Scratch for router logits [TOKENS, EXPERTS] (25.2 MB). Device globals are the
// allowed scratch mechanism (no cudaMalloc permitted).
__device__ float g_logits[(size_t)TOKENS * EXPERTS];

// ---------------------------------------------------------------------------
// GEMM: logits[m][e] = sum_k A[m][k] * W[e][k]   (both row-major, K contiguous)
// 128x128 block tile, K-tile 8, 256 threads, 8x8 per-thread microtile.
// ---------------------------------------------------------------------------
#define BM 128
#define BN 128
#define BK 8

__global__ __launch_bounds__(256, 2)
void router_gemm_kernel(const float* __restrict__ A, const float* __restrict__ B) {
    // +4 padding (stride 132 floats): breaks the 2-way bank conflict between the
    // lc=0 / lc=4 writer halves (528 mod 32 = 16) and keeps float4 alignment.
    __shared__ float As[BK][BM + 4];
    __shared__ float Bs[BK][BN + 4];

    const int tid = threadIdx.x;
    const int m0  = blockIdx.y * BM;
    const int n0  = blockIdx.x * BN;

    const int lr = tid >> 1;         // 0..127 : row within tile
    const int lc = (tid & 1) * 4;    // 0 or 4 : k sub-offset

    const int ty = tid >> 4;         // 0..15
    const int tx = tid & 15;         // 0..15

    float acc[8][8];
    #pragma unroll
    for (int i = 0; i < 8; i++)
        #pragma unroll
        for (int j = 0; j < 8; j++) acc[i][j] = 0.0f;

    const float* Aptr = A + (size_t)(m0 + lr) * HIDDEN + lc;
    const float* Bptr = B + (size_t)(n0 + lr) * HIDDEN + lc;

    for (int k0 = 0; k0 < HIDDEN; k0 += BK) {
        float4 av = *(const float4*)(Aptr + k0);
        float4 bv = *(const float4*)(Bptr + k0);
        As[lc + 0][lr] = av.x; As[lc + 1][lr] = av.y;
        As[lc + 2][lr] = av.z; As[lc + 3][lr] = av.w;
        Bs[lc + 0][lr] = bv.x; Bs[lc + 1][lr] = bv.y;
        Bs[lc + 2][lr] = bv.z; Bs[lc + 3][lr] = bv.w;
        __syncthreads();

        #pragma unroll
        for (int k = 0; k < BK; k++) {
            float a[8], b[8];
            *(float4*)&a[0] = *(const float4*)&As[k][ty * 8];
            *(float4*)&a[4] = *(const float4*)&As[k][ty * 8 + 4];
            *(float4*)&b[0] = *(const float4*)&Bs[k][tx * 8];
            *(float4*)&b[4] = *(const float4*)&Bs[k][tx * 8 + 4];
            #pragma unroll
            for (int i = 0; i < 8; i++)
                #pragma unroll
                for (int j = 0; j < 8; j++)
                    acc[i][j] = fmaf(a[i], b[j], acc[i][j]);
        }
        __syncthreads();
    }

    float* C = g_logits + (size_t)(m0 + ty * 8) * EXPERTS + (n0 + tx * 8);
    #pragma unroll
    for (int i = 0; i < 8; i++) {
        *(float4*)(C + (size_t)i * EXPERTS)     = make_float4(acc[i][0], acc[i][1], acc[i][2], acc[i][3]);
        *(float4*)(C + (size_t)i * EXPERTS + 4) = make_float4(acc[i][4], acc[i][5], acc[i][6], acc[i][7]);
    }
}

// ---------------------------------------------------------------------------
// Softmax + bias-corrected top-12 per token. One block (256 thr) per token;
// each thread owns 3 experts: tid, tid+256, tid+512.
// Tie-break: lower expert index wins (lax.top_k semantics).
// Output layout (fp32): [0, T*12)            = indices (as float)
//                       [T*12, 2*T*12)       = weights (= score * 2.5)
// ---------------------------------------------------------------------------
__global__ __launch_bounds__(256)
void topk_kernel(const float* __restrict__ bias, float* __restrict__ out) {
    const int token = blockIdx.x;
    const int tid   = threadIdx.x;
    const float* row = g_logits + (size_t)token * EXPERTS;

    float z[3], sc[3], bsc[3];
    #pragma unroll
    for (int i = 0; i < 3; i++) z[i] = row[tid + i * 256];

    __shared__ float red[8];
    __shared__ float wv[8];
    __shared__ int   wi[8];
    __shared__ int   s_best_i;

    // --- block max ---
    float m = fmaxf(z[0], fmaxf(z[1], z[2]));
    #pragma unroll
    for (int off = 16; off; off >>= 1)
        m = fmaxf(m, __shfl_xor_sync(0xffffffffu, m, off));
    if ((tid & 31) == 0) red[tid >> 5] = m;
    __syncthreads();
    m = red[0];
    #pragma unroll
    for (int w = 1; w < 8; w++) m = fmaxf(m, red[w]);
    __syncthreads();

    // --- block sum of exp ---
    float s = 0.0f;
    #pragma unroll
    for (int i = 0; i < 3; i++) { sc[i] = expf(z[i] - m); s += sc[i]; }
    #pragma unroll
    for (int off = 16; off; off >>= 1)
        s += __shfl_xor_sync(0xffffffffu, s, off);
    if ((tid & 31) == 0) red[tid >> 5] = s;
    __syncthreads();
    s = 0.0f;
    #pragma unroll
    for (int w = 0; w < 8; w++) s += red[w];
    const float inv = 1.0f / s;
    #pragma unroll
    for (int i = 0; i < 3; i++) {
        sc[i] *= inv;
        bsc[i] = sc[i] + bias[tid + i * 256];
    }

    // --- 12 rounds of block argmax over biased scores ---
    for (int sel = 0; sel < TOPK; sel++) {
        // local best of 3 (strict > keeps lowest expert index: slots are ascending)
        float v  = bsc[0]; int li = 0;
        if (bsc[1] > v) { v = bsc[1]; li = 1; }
        if (bsc[2] > v) { v = bsc[2]; li = 2; }
        int idx = tid + li * 256;

        // warp argmax (tie -> smaller index)
        #pragma unroll
        for (int off = 16; off; off >>= 1) {
            float ov = __shfl_xor_sync(0xffffffffu, v,   off);
            int   oi = __shfl_xor_sync(0xffffffffu, idx, off);
            if (ov > v || (ov == v && oi < idx)) { v = ov; idx = oi; }
        }
        if ((tid & 31) == 0) { wv[tid >> 5] = v; wi[tid >> 5] = idx; }
        __syncthreads();

        if (tid == 0) {
            float bvv = wv[0]; int bi = wi[0];
            #pragma unroll
            for (int w = 1; w < 8; w++) {
                if (wv[w] > bvv || (wv[w] == bvv && wi[w] < bi)) { bvv = wv[w]; bi = wi[w]; }
            }
            s_best_i = bi;
        }
        __syncthreads();

        const int e = s_best_i;
        if ((e & 255) == tid) {
            const int slot = e >> 8;
            out[(size_t)token * TOPK + sel]                         = (float)e;
            out[(size_t)TOKENS * TOPK + (size_t)token * TOPK + sel] = sc[slot] * RSCALE;
            bsc[slot] = -CUDART_INF_F;
        }
        // next iteration's __syncthreads (after wv/wi writes) protects s_best_i reuse
    }
}

extern "C" void kernel_launch(void* const* d_in, const int* in_sizes, int n_in,
                              void* d_out, int out_size) {
    const float* A    = (const float*)d_in[0];  // hidden_states [8192, 6144]
    const float* W    = (const float*)d_in[1];  // classifier_weight [768, 6144]
    const float* bias = (const float*)d_in[2];  // e_score_correction_bias [768]
    float* out = (float*)d_out;

    dim3 grid(EXPERTS / BN, TOKENS / BM);
    router_gemm_kernel<<<grid, 256>>>(A, W);
    topk_kernel<<<TOKENS, 256>>>(bias, out);
}

// round 5
// speedup vs baseline: 1.3215x; 1.3215x over previous
#include <cuda_runtime.h>
#include <math_constants.h>
#include <cstdint>

#define TOKENS  8192
#define HIDDEN  6144
#define EXPERTS 768
#define TOPK    12
#define NCAND   13
#define RSCALE  2.5f
#define TAU     1e-4f

// ---------------- GEMM config ----------------
#define BM 128
#define BN 128
#define BK 16
#define NSTAGES (HIDDEN / BK)   // 384
#define SSTRIDE 20              // smem row stride in floats (conflict-free frag gather)
#define TILE_F  (128 * SSTRIDE)
#define BUF_F   (4 * TILE_F)
#define SMEM_BYTES (2 * BUF_F * 4)  // 81920

__device__ float g_logits[(size_t)TOKENS * EXPERTS];

// ---------------- helpers ----------------
__device__ __forceinline__ void tf32_split(float x, float& hi, float& lo) {
    uint32_t h;
    asm("cvt.rna.tf32.f32 %0, %1;" : "=r"(h) : "f"(x));
    hi = __uint_as_float(h);
    float r = x - hi;
    asm("cvt.rna.tf32.f32 %0, %1;" : "=r"(h) : "f"(r));
    lo = __uint_as_float(h);
}

__device__ __forceinline__ void mma8(float* c, const uint32_t* a, const uint32_t* b) {
    asm volatile(
        "mma.sync.aligned.m16n8k8.row.col.f32.tf32.tf32.f32 "
        "{%0,%1,%2,%3}, {%4,%5,%6,%7}, {%8,%9}, {%0,%1,%2,%3};"
        : "+f"(c[0]), "+f"(c[1]), "+f"(c[2]), "+f"(c[3])
        : "r"(a[0]), "r"(a[1]), "r"(a[2]), "r"(a[3]), "r"(b[0]), "r"(b[1]));
}
// t = a*b + 0  (fresh small-magnitude accumulator: no alignment truncation loss)
__device__ __forceinline__ void mma8_zero(float* t, const uint32_t* a, const uint32_t* b) {
    asm volatile(
        "mma.sync.aligned.m16n8k8.row.col.f32.tf32.tf32.f32 "
        "{%0,%1,%2,%3}, {%4,%5,%6,%7}, {%8,%9}, {%10,%11,%12,%13};"
        : "=f"(t[0]), "=f"(t[1]), "=f"(t[2]), "=f"(t[3])
        : "r"(a[0]), "r"(a[1]), "r"(a[2]), "r"(a[3]), "r"(b[0]), "r"(b[1]),
          "f"(0.0f), "f"(0.0f), "f"(0.0f), "f"(0.0f));
}

// ---------------------------------------------------------------------------
// 3xTF32 mma.sync GEMM with separated correction accumulation.
// ---------------------------------------------------------------------------
__global__ __launch_bounds__(256, 1)
void router_gemm_mma(const float* __restrict__ A, const float* __restrict__ B) {
    extern __shared__ float sm[];
    const int tid  = threadIdx.x;
    const int wid  = tid >> 5;
    const int lane = tid & 31;
    const int m0 = blockIdx.y * BM;
    const int n0 = blockIdx.x * BN;

    const int wm = wid & 1;
    const int wn = wid >> 1;

    const int r0 = tid >> 2, kq0 = (tid & 3) * 4;
    const int r1 = (tid + 256) >> 2, kq1 = kq0;

    const float* Abase = A + (size_t)m0 * HIDDEN;
    const float* Bbase = B + (size_t)n0 * HIDDEN;

    float acc[4][4][4];
    #pragma unroll
    for (int mi = 0; mi < 4; mi++)
        #pragma unroll
        for (int ni = 0; ni < 4; ni++)
            #pragma unroll
            for (int j = 0; j < 4; j++) acc[mi][ni][j] = 0.0f;

    float4 pa0, pa1, pb0, pb1;

    pa0 = *(const float4*)(Abase + (size_t)r0 * HIDDEN + kq0);
    pa1 = *(const float4*)(Abase + (size_t)r1 * HIDDEN + kq1);
    pb0 = *(const float4*)(Bbase + (size_t)r0 * HIDDEN + kq0);
    pb1 = *(const float4*)(Bbase + (size_t)r1 * HIDDEN + kq1);
    {
        float* Ah = sm;                float* Al = sm + TILE_F;
        float* Bh = sm + 2 * TILE_F;   float* Bl = sm + 3 * TILE_F;
        float4 h, l;
        tf32_split(pa0.x, h.x, l.x); tf32_split(pa0.y, h.y, l.y);
        tf32_split(pa0.z, h.z, l.z); tf32_split(pa0.w, h.w, l.w);
        *(float4*)(Ah + r0 * SSTRIDE + kq0) = h; *(float4*)(Al + r0 * SSTRIDE + kq0) = l;
        tf32_split(pa1.x, h.x, l.x); tf32_split(pa1.y, h.y, l.y);
        tf32_split(pa1.z, h.z, l.z); tf32_split(pa1.w, h.w, l.w);
        *(float4*)(Ah + r1 * SSTRIDE + kq1) = h; *(float4*)(Al + r1 * SSTRIDE + kq1) = l;
        tf32_split(pb0.x, h.x, l.x); tf32_split(pb0.y, h.y, l.y);
        tf32_split(pb0.z, h.z, l.z); tf32_split(pb0.w, h.w, l.w);
        *(float4*)(Bh + r0 * SSTRIDE + kq0) = h; *(float4*)(Bl + r0 * SSTRIDE + kq0) = l;
        tf32_split(pb1.x, h.x, l.x); tf32_split(pb1.y, h.y, l.y);
        tf32_split(pb1.z, h.z, l.z); tf32_split(pb1.w, h.w, l.w);
        *(float4*)(Bh + r1 * SSTRIDE + kq1) = h; *(float4*)(Bl + r1 * SSTRIDE + kq1) = l;
    }
    __syncthreads();

    const int arow0 = wm * 64 + (lane >> 2);
    const int brow0 = wn * 32 + (lane >> 2);
    const int kfrag = lane & 3;

    for (int s = 0; s < NSTAGES; s++) {
        const int buf = s & 1;

        if (s + 1 < NSTAGES) {
            const int k0 = (s + 1) * BK;
            pa0 = *(const float4*)(Abase + (size_t)r0 * HIDDEN + k0 + kq0);
            pa1 = *(const float4*)(Abase + (size_t)r1 * HIDDEN + k0 + kq1);
            pb0 = *(const float4*)(Bbase + (size_t)r0 * HIDDEN + k0 + kq0);
            pb1 = *(const float4*)(Bbase + (size_t)r1 * HIDDEN + k0 + kq1);
        }

        const float* Ah = sm + buf * BUF_F;
        const float* Al = Ah + TILE_F;
        const float* Bh = Ah + 2 * TILE_F;
        const float* Bl = Ah + 3 * TILE_F;

        #pragma unroll
        for (int h = 0; h < 2; h++) {
            const int kb = h * 8 + kfrag;
            uint32_t ah[4][4], al[4][4], bh[4][2], bl[4][2];
            #pragma unroll
            for (int mi = 0; mi < 4; mi++) {
                const int ra = (arow0 + mi * 16) * SSTRIDE + kb;
                ah[mi][0] = __float_as_uint(Ah[ra]);
                ah[mi][1] = __float_as_uint(Ah[ra + 8 * SSTRIDE]);
                ah[mi][2] = __float_as_uint(Ah[ra + 4]);
                ah[mi][3] = __float_as_uint(Ah[ra + 8 * SSTRIDE + 4]);
                al[mi][0] = __float_as_uint(Al[ra]);
                al[mi][1] = __float_as_uint(Al[ra + 8 * SSTRIDE]);
                al[mi][2] = __float_as_uint(Al[ra + 4]);
                al[mi][3] = __float_as_uint(Al[ra + 8 * SSTRIDE + 4]);
            }
            #pragma unroll
            for (int ni = 0; ni < 4; ni++) {
                const int rb = (brow0 + ni * 8) * SSTRIDE + kb;
                bh[ni][0] = __float_as_uint(Bh[rb]);
                bh[ni][1] = __float_as_uint(Bh[rb + 4]);
                bl[ni][0] = __float_as_uint(Bl[rb]);
                bl[ni][1] = __float_as_uint(Bl[rb + 4]);
            }
            #pragma unroll
            for (int mi = 0; mi < 4; mi++)
                #pragma unroll
                for (int ni = 0; ni < 4; ni++) {
                    mma8(acc[mi][ni], ah[mi], bh[ni]);     // hi*hi -> main acc
                    float t[4];
                    mma8_zero(t, ah[mi], bl[ni]);          // t  = hi*lo
                    mma8(t, al[mi], bh[ni]);               // t += lo*hi
                    #pragma unroll
                    for (int j = 0; j < 4; j++) acc[mi][ni][j] += t[j];
                }
        }

        if (s + 1 < NSTAGES) {
            float* nAh = sm + (buf ^ 1) * BUF_F;
            float* nAl = nAh + TILE_F;
            float* nBh = nAh + 2 * TILE_F;
            float* nBl = nAh + 3 * TILE_F;
            float4 h, l;
            tf32_split(pa0.x, h.x, l.x); tf32_split(pa0.y, h.y, l.y);
            tf32_split(pa0.z, h.z, l.z); tf32_split(pa0.w, h.w, l.w);
            *(float4*)(nAh + r0 * SSTRIDE + kq0) = h; *(float4*)(nAl + r0 * SSTRIDE + kq0) = l;
            tf32_split(pa1.x, h.x, l.x); tf32_split(pa1.y, h.y, l.y);
            tf32_split(pa1.z, h.z, l.z); tf32_split(pa1.w, h.w, l.w);
            *(float4*)(nAh + r1 * SSTRIDE + kq1) = h; *(float4*)(nAl + r1 * SSTRIDE + kq1) = l;
            tf32_split(pb0.x, h.x, l.x); tf32_split(pb0.y, h.y, l.y);
            tf32_split(pb0.z, h.z, l.z); tf32_split(pb0.w, h.w, l.w);
            *(float4*)(nBh + r0 * SSTRIDE + kq0) = h; *(float4*)(nBl + r0 * SSTRIDE + kq0) = l;
            tf32_split(pb1.x, h.x, l.x); tf32_split(pb1.y, h.y, l.y);
            tf32_split(pb1.z, h.z, l.z); tf32_split(pb1.w, h.w, l.w);
            *(float4*)(nBh + r1 * SSTRIDE + kq1) = h; *(float4*)(nBl + r1 * SSTRIDE + kq1) = l;
        }
        __syncthreads();
    }

    #pragma unroll
    for (int mi = 0; mi < 4; mi++) {
        const int row = m0 + wm * 64 + mi * 16 + (lane >> 2);
        #pragma unroll
        for (int ni = 0; ni < 4; ni++) {
            const int col = n0 + wn * 32 + ni * 8 + (lane & 3) * 2;
            *(float2*)(g_logits + (size_t)row * EXPERTS + col)       = make_float2(acc[mi][ni][0], acc[mi][ni][1]);
            *(float2*)(g_logits + (size_t)(row + 8) * EXPERTS + col) = make_float2(acc[mi][ni][2], acc[mi][ni][3]);
        }
    }
}

// ---------------------------------------------------------------------------
// Softmax + top-13 candidates + exact rescore of tight boundary pairs + sort.
// ---------------------------------------------------------------------------
__global__ __launch_bounds__(256)
void topk_kernel(const float* __restrict__ A, const float* __restrict__ W,
                 const float* __restrict__ bias, float* __restrict__ out) {
    const int token = blockIdx.x;
    const int tid   = threadIdx.x;
    const float* row = g_logits + (size_t)token * EXPERTS;

    float z[3], sc[3], bsc[3];
    #pragma unroll
    for (int i = 0; i < 3; i++) z[i] = row[tid + i * 256];

    __shared__ float red[8];
    __shared__ float wv[8];
    __shared__ int   wi[8];
    __shared__ int   s_best_i;
    __shared__ float s_m, s_inv;
    __shared__ int   cand_i[NCAND];
    __shared__ float cand_s[NCAND];
    __shared__ float cand_b[NCAND];
    __shared__ int   s_fl[NCAND];
    __shared__ int   s_nfl;

    // block max
    float m = fmaxf(z[0], fmaxf(z[1], z[2]));
    #pragma unroll
    for (int off = 16; off; off >>= 1)
        m = fmaxf(m, __shfl_xor_sync(0xffffffffu, m, off));
    if ((tid & 31) == 0) red[tid >> 5] = m;
    __syncthreads();
    m = red[0];
    #pragma unroll
    for (int w = 1; w < 8; w++) m = fmaxf(m, red[w]);
    __syncthreads();

    // block sum of exp
    float s = 0.0f;
    #pragma unroll
    for (int i = 0; i < 3; i++) { sc[i] = expf(z[i] - m); s += sc[i]; }
    #pragma unroll
    for (int off = 16; off; off >>= 1)
        s += __shfl_xor_sync(0xffffffffu, s, off);
    if ((tid & 31) == 0) red[tid >> 5] = s;
    __syncthreads();
    s = 0.0f;
    #pragma unroll
    for (int w = 0; w < 8; w++) s += red[w];
    const float inv = 1.0f / s;
    if (tid == 0) { s_m = m; s_inv = inv; }
    #pragma unroll
    for (int i = 0; i < 3; i++) {
        sc[i] *= inv;
        bsc[i] = sc[i] + bias[tid + i * 256];
    }

    // 13 rounds of block argmax
    for (int sel = 0; sel < NCAND; sel++) {
        float v  = bsc[0]; int li = 0;
        if (bsc[1] > v) { v = bsc[1]; li = 1; }
        if (bsc[2] > v) { v = bsc[2]; li = 2; }
        int idx = tid + li * 256;

        #pragma unroll
        for (int off = 16; off; off >>= 1) {
            float ov = __shfl_xor_sync(0xffffffffu, v,   off);
            int   oi = __shfl_xor_sync(0xffffffffu, idx, off);
            if (ov > v || (ov == v && oi < idx)) { v = ov; idx = oi; }
        }
        if ((tid & 31) == 0) { wv[tid >> 5] = v; wi[tid >> 5] = idx; }
        __syncthreads();

        if (tid == 0) {
            float bvv = wv[0]; int bi = wi[0];
            #pragma unroll
            for (int w = 1; w < 8; w++)
                if (wv[w] > bvv || (wv[w] == bvv && wi[w] < bi)) { bvv = wv[w]; bi = wi[w]; }
            s_best_i = bi;
        }
        __syncthreads();

        const int e = s_best_i;
        if ((e & 255) == tid) {
            const int slot = e >> 8;
            cand_i[sel] = e;
            cand_s[sel] = sc[slot];
            cand_b[sel] = bsc[slot];
            bsc[slot] = -CUDART_INF_F;
        }
        __syncthreads();
    }

    // flag tight adjacent pairs (cand_b is descending)
    if (tid == 0) {
        int flg[NCAND];
        #pragma unroll
        for (int r = 0; r < NCAND; r++) flg[r] = 0;
        for (int r = 0; r < NCAND - 1; r++)
            if (cand_b[r] - cand_b[r + 1] < TAU) { flg[r] = 1; flg[r + 1] = 1; }
        int n = 0;
        for (int r = 0; r < NCAND; r++) if (flg[r]) s_fl[n++] = r;
        s_nfl = n;
    }
    __syncthreads();

    const int nf = s_nfl;
    const float* x = A + (size_t)token * HIDDEN;
    for (int f = 0; f < nf; f++) {
        const int slot = s_fl[f];
        const int e = cand_i[slot];
        const float* w = W + (size_t)e * HIDDEN;
        float p = 0.0f;
        #pragma unroll 8
        for (int j = tid; j < HIDDEN; j += 256)
            p = fmaf(x[j], w[j], p);
        #pragma unroll
        for (int off = 16; off; off >>= 1)
            p += __shfl_xor_sync(0xffffffffu, p, off);
        if ((tid & 31) == 0) red[tid >> 5] = p;
        __syncthreads();
        if (tid == 0) {
            float zex = 0.0f;
            #pragma unroll
            for (int w8 = 0; w8 < 8; w8++) zex += red[w8];
            float sn = expf(zex - s_m) * s_inv;
            cand_s[slot] = sn;
            cand_b[slot] = sn + bias[e];
        }
        __syncthreads();
    }

    // insertion sort (desc biased score, tie -> lower index) + emit top-12
    if (tid == 0) {
        for (int i = 1; i < NCAND; i++) {
            float kb = cand_b[i], ks = cand_s[i]; int ki = cand_i[i];
            int j = i - 1;
            while (j >= 0 && (cand_b[j] < kb || (cand_b[j] == kb && cand_i[j] > ki))) {
                cand_b[j + 1] = cand_b[j]; cand_s[j + 1] = cand_s[j]; cand_i[j + 1] = cand_i[j];
                j--;
            }
            cand_b[j + 1] = kb; cand_s[j + 1] = ks; cand_i[j + 1] = ki;
        }
        #pragma unroll
        for (int r = 0; r < TOPK; r++) {
            out[(size_t)token * TOPK + r]                       = (float)cand_i[r];
            out[(size_t)TOKENS * TOPK + (size_t)token * TOPK + r] = cand_s[r] * RSCALE;
        }
    }
}

extern "C" void kernel_launch(void* const* d_in, const int* in_sizes, int n_in,
                              void* d_out, int out_size) {
    const float* A    = (const float*)d_in[0];
    const float* W    = (const float*)d_in[1];
    const float* bias = (const float*)d_in[2];
    float* out = (float*)d_out;

    cudaFuncSetAttribute(router_gemm_mma, cudaFuncAttributeMaxDynamicSharedMemorySize, SMEM_BYTES);

    dim3 grid(EXPERTS / BN, TOKENS / BM);
    router_gemm_mma<<<grid, 256, SMEM_BYTES>>>(A, W);
    topk_kernel<<<TOKENS, 256>>>(A, W, bias, out);
}

// round 6
// speedup vs baseline: 1.9793x; 1.4978x over previous
#include <cuda_runtime.h>
#include <cuda_fp16.h>
#include <math_constants.h>
#include <cstdint>

#define TOKENS  8192
#define HIDDEN  6144
#define EXPERTS 768
#define TOPK    12
#define NCAND   13
#define RSCALE  2.5f
#define TAU     1e-4f

// ---------------- GEMM config ----------------
#define BM 128
#define BN 64
#define BK 16
#define NSTAGES (HIDDEN / BK)   // 384
#define ROWW 12                 // 8B-words per smem row (8 used + 4 pad): conflict-free

__device__ float g_logits[(size_t)TOKENS * EXPERTS];

// ---------------- helpers ----------------
__device__ __forceinline__ uint32_t pack_h2(__half a, __half b) {
    return (uint32_t)__half_as_ushort(a) | ((uint32_t)__half_as_ushort(b) << 16);
}
// float4 -> {hi01, lo01, hi23, lo23} fp16x2 words
__device__ __forceinline__ uint4 split_f4(float4 v) {
    __half h0 = __float2half_rn(v.x), h1 = __float2half_rn(v.y);
    __half h2 = __float2half_rn(v.z), h3 = __float2half_rn(v.w);
    __half l0 = __float2half_rn(v.x - __half2float(h0));
    __half l1 = __float2half_rn(v.y - __half2float(h1));
    __half l2 = __float2half_rn(v.z - __half2float(h2));
    __half l3 = __float2half_rn(v.w - __half2float(h3));
    uint4 r;
    r.x = pack_h2(h0, h1); r.y = pack_h2(l0, l1);
    r.z = pack_h2(h2, h3); r.w = pack_h2(l2, l3);
    return r;
}

__device__ __forceinline__ void mma16(float* c, const uint32_t* a, const uint32_t* b) {
    asm volatile(
        "mma.sync.aligned.m16n8k16.row.col.f32.f16.f16.f32 "
        "{%0,%1,%2,%3}, {%4,%5,%6,%7}, {%8,%9}, {%0,%1,%2,%3};"
        : "+f"(c[0]), "+f"(c[1]), "+f"(c[2]), "+f"(c[3])
        : "r"(a[0]), "r"(a[1]), "r"(a[2]), "r"(a[3]), "r"(b[0]), "r"(b[1]));
}

// ---------------------------------------------------------------------------
// fp16x3 mma.sync GEMM: logits[m][e] = sum_k A[m][k] * W[e][k]
// hi*hi -> acc ; hi*lo + lo*hi -> acc_c (separate accumulator, added once).
// ---------------------------------------------------------------------------
__global__ __launch_bounds__(256, 2)
void router_gemm_fp16(const float* __restrict__ A, const float* __restrict__ B) {
    __shared__ unsigned long long smA[2][BM * ROWW];  // 24 KB
    __shared__ unsigned long long smB[2][BN * ROWW];  // 12 KB

    const int tid  = threadIdx.x;
    const int wid  = tid >> 5;
    const int lane = tid & 31;
    const int m0 = blockIdx.y * BM;
    const int n0 = blockIdx.x * BN;

    const int wm = wid & 3;    // 4 bands of 32 rows
    const int wn = wid >> 2;   // 2 bands of 32 cols

    // gmem->smem map: A slots tid, tid+256 over 512 float4; B slot tid over 256.
    const int ar0 = tid >> 2,        akq = (tid & 3);          // j0 = akq*2
    const int ar1 = (tid + 256) >> 2;                           // same akq
    const int br0 = tid >> 2;                                   // B: 64 rows x 4 float4

    const float* Abase = A + (size_t)m0 * HIDDEN;
    const float* Bbase = B + (size_t)n0 * HIDDEN;

    float acc[2][4][4], accc[2][4][4];
    #pragma unroll
    for (int mi = 0; mi < 2; mi++)
        #pragma unroll
        for (int ni = 0; ni < 4; ni++)
            #pragma unroll
            for (int j = 0; j < 4; j++) { acc[mi][ni][j] = 0.0f; accc[mi][ni][j] = 0.0f; }

    float4 pa0, pa1, pb0;

    // prologue: stage 0
    pa0 = *(const float4*)(Abase + (size_t)ar0 * HIDDEN + akq * 4);
    pa1 = *(const float4*)(Abase + (size_t)ar1 * HIDDEN + akq * 4);
    pb0 = *(const float4*)(Bbase + (size_t)br0 * HIDDEN + akq * 4);
    *(uint4*)&smA[0][ar0 * ROWW + akq * 2] = split_f4(pa0);
    *(uint4*)&smA[0][ar1 * ROWW + akq * 2] = split_f4(pa1);
    *(uint4*)&smB[0][br0 * ROWW + akq * 2] = split_f4(pb0);
    __syncthreads();

    const int rq = lane >> 2;   // 0..7
    const int jl = lane & 3;    // k-pair 0..3 (and +4)

    for (int s = 0; s < NSTAGES; s++) {
        const int buf = s & 1;

        if (s + 1 < NSTAGES) {
            const int k0 = (s + 1) * BK;
            pa0 = *(const float4*)(Abase + (size_t)ar0 * HIDDEN + k0 + akq * 4);
            pa1 = *(const float4*)(Abase + (size_t)ar1 * HIDDEN + k0 + akq * 4);
            pb0 = *(const float4*)(Bbase + (size_t)br0 * HIDDEN + k0 + akq * 4);
        }

        // ---- fragment loads (LDS.64: hi-pair in low word, lo-pair in high) ----
        uint32_t ah[2][4], al[2][4], bh[4][2], bl[4][2];
        #pragma unroll
        for (int mi = 0; mi < 2; mi++) {
            const int ra = (wm * 32 + mi * 16 + rq) * ROWW;
            unsigned long long q0 = smA[buf][ra + jl];
            unsigned long long q1 = smA[buf][ra + 8 * ROWW + jl];
            unsigned long long q2 = smA[buf][ra + jl + 4];
            unsigned long long q3 = smA[buf][ra + 8 * ROWW + jl + 4];
            ah[mi][0] = (uint32_t)q0; al[mi][0] = (uint32_t)(q0 >> 32);
            ah[mi][1] = (uint32_t)q1; al[mi][1] = (uint32_t)(q1 >> 32);
            ah[mi][2] = (uint32_t)q2; al[mi][2] = (uint32_t)(q2 >> 32);
            ah[mi][3] = (uint32_t)q3; al[mi][3] = (uint32_t)(q3 >> 32);
        }
        #pragma unroll
        for (int ni = 0; ni < 4; ni++) {
            const int rb = (wn * 32 + ni * 8 + rq) * ROWW;
            unsigned long long q0 = smB[buf][rb + jl];
            unsigned long long q1 = smB[buf][rb + jl + 4];
            bh[ni][0] = (uint32_t)q0; bl[ni][0] = (uint32_t)(q0 >> 32);
            bh[ni][1] = (uint32_t)q1; bl[ni][1] = (uint32_t)(q1 >> 32);
        }

        // ---- 24 mmas: hi*hi -> acc, cross terms -> accc ----
        #pragma unroll
        for (int mi = 0; mi < 2; mi++)
            #pragma unroll
            for (int ni = 0; ni < 4; ni++) {
                mma16(acc[mi][ni],  ah[mi], bh[ni]);
                mma16(accc[mi][ni], ah[mi], bl[ni]);
                mma16(accc[mi][ni], al[mi], bh[ni]);
            }

        // ---- STS for stage s+1 ----
        if (s + 1 < NSTAGES) {
            const int nb = buf ^ 1;
            *(uint4*)&smA[nb][ar0 * ROWW + akq * 2] = split_f4(pa0);
            *(uint4*)&smA[nb][ar1 * ROWW + akq * 2] = split_f4(pa1);
            *(uint4*)&smB[nb][br0 * ROWW + akq * 2] = split_f4(pb0);
        }
        __syncthreads();
    }

    // ---- epilogue ----
    #pragma unroll
    for (int mi = 0; mi < 2; mi++) {
        const int row = m0 + wm * 32 + mi * 16 + rq;
        #pragma unroll
        for (int ni = 0; ni < 4; ni++) {
            const int col = n0 + wn * 32 + ni * 8 + jl * 2;
            float c0 = acc[mi][ni][0] + accc[mi][ni][0];
            float c1 = acc[mi][ni][1] + accc[mi][ni][1];
            float c2 = acc[mi][ni][2] + accc[mi][ni][2];
            float c3 = acc[mi][ni][3] + accc[mi][ni][3];
            *(float2*)(g_logits + (size_t)row * EXPERTS + col)       = make_float2(c0, c1);
            *(float2*)(g_logits + (size_t)(row + 8) * EXPERTS + col) = make_float2(c2, c3);
        }
    }
}

// ---------------------------------------------------------------------------
// Softmax + top-13 candidates + exact rescore of tight pairs + sort (R5, passing).
// ---------------------------------------------------------------------------
__global__ __launch_bounds__(256)
void topk_kernel(const float* __restrict__ A, const float* __restrict__ W,
                 const float* __restrict__ bias, float* __restrict__ out) {
    const int token = blockIdx.x;
    const int tid   = threadIdx.x;
    const float* row = g_logits + (size_t)token * EXPERTS;

    float z[3], sc[3], bsc[3];
    #pragma unroll
    for (int i = 0; i < 3; i++) z[i] = row[tid + i * 256];

    __shared__ float red[8];
    __shared__ float wv[8];
    __shared__ int   wi[8];
    __shared__ int   s_best_i;
    __shared__ float s_m, s_inv;
    __shared__ int   cand_i[NCAND];
    __shared__ float cand_s[NCAND];
    __shared__ float cand_b[NCAND];
    __shared__ int   s_fl[NCAND];
    __shared__ int   s_nfl;

    float m = fmaxf(z[0], fmaxf(z[1], z[2]));
    #pragma unroll
    for (int off = 16; off; off >>= 1)
        m = fmaxf(m, __shfl_xor_sync(0xffffffffu, m, off));
    if ((tid & 31) == 0) red[tid >> 5] = m;
    __syncthreads();
    m = red[0];
    #pragma unroll
    for (int w = 1; w < 8; w++) m = fmaxf(m, red[w]);
    __syncthreads();

    float s = 0.0f;
    #pragma unroll
    for (int i = 0; i < 3; i++) { sc[i] = expf(z[i] - m); s += sc[i]; }
    #pragma unroll
    for (int off = 16; off; off >>= 1)
        s += __shfl_xor_sync(0xffffffffu, s, off);
    if ((tid & 31) == 0) red[tid >> 5] = s;
    __syncthreads();
    s = 0.0f;
    #pragma unroll
    for (int w = 0; w < 8; w++) s += red[w];
    const float inv = 1.0f / s;
    if (tid == 0) { s_m = m; s_inv = inv; }
    #pragma unroll
    for (int i = 0; i < 3; i++) {
        sc[i] *= inv;
        bsc[i] = sc[i] + bias[tid + i * 256];
    }

    for (int sel = 0; sel < NCAND; sel++) {
        float v  = bsc[0]; int li = 0;
        if (bsc[1] > v) { v = bsc[1]; li = 1; }
        if (bsc[2] > v) { v = bsc[2]; li = 2; }
        int idx = tid + li * 256;

        #pragma unroll
        for (int off = 16; off; off >>= 1) {
            float ov = __shfl_xor_sync(0xffffffffu, v,   off);
            int   oi = __shfl_xor_sync(0xffffffffu, idx, off);
            if (ov > v || (ov == v && oi < idx)) { v = ov; idx = oi; }
        }
        if ((tid & 31) == 0) { wv[tid >> 5] = v; wi[tid >> 5] = idx; }
        __syncthreads();

        if (tid == 0) {
            float bvv = wv[0]; int bi = wi[0];
            #pragma unroll
            for (int w = 1; w < 8; w++)
                if (wv[w] > bvv || (wv[w] == bvv && wi[w] < bi)) { bvv = wv[w]; bi = wi[w]; }
            s_best_i = bi;
        }
        __syncthreads();

        const int e = s_best_i;
        if ((e & 255) == tid) {
            const int slot = e >> 8;
            cand_i[sel] = e;
            cand_s[sel] = sc[slot];
            cand_b[sel] = bsc[slot];
            bsc[slot] = -CUDART_INF_F;
        }
        __syncthreads();
    }

    if (tid == 0) {
        int flg[NCAND];
        #pragma unroll
        for (int r = 0; r < NCAND; r++) flg[r] = 0;
        for (int r = 0; r < NCAND - 1; r++)
            if (cand_b[r] - cand_b[r + 1] < TAU) { flg[r] = 1; flg[r + 1] = 1; }
        int n = 0;
        for (int r = 0; r < NCAND; r++) if (flg[r]) s_fl[n++] = r;
        s_nfl = n;
    }
    __syncthreads();

    const int nf = s_nfl;
    const float* x = A + (size_t)token * HIDDEN;
    for (int f = 0; f < nf; f++) {
        const int slot = s_fl[f];
        const int e = cand_i[slot];
        const float* w = W + (size_t)e * HIDDEN;
        float p = 0.0f;
        #pragma unroll 8
        for (int j = tid; j < HIDDEN; j += 256)
            p = fmaf(x[j], w[j], p);
        #pragma unroll
        for (int off = 16; off; off >>= 1)
            p += __shfl_xor_sync(0xffffffffu, p, off);
        if ((tid & 31) == 0) red[tid >> 5] = p;
        __syncthreads();
        if (tid == 0) {
            float zex = 0.0f;
            #pragma unroll
            for (int w8 = 0; w8 < 8; w8++) zex += red[w8];
            float sn = expf(zex - s_m) * s_inv;
            cand_s[slot] = sn;
            cand_b[slot] = sn + bias[e];
        }
        __syncthreads();
    }

    if (tid == 0) {
        for (int i = 1; i < NCAND; i++) {
            float kb = cand_b[i], ks = cand_s[i]; int ki = cand_i[i];
            int j = i - 1;
            while (j >= 0 && (cand_b[j] < kb || (cand_b[j] == kb && cand_i[j] > ki))) {
                cand_b[j + 1] = cand_b[j]; cand_s[j + 1] = cand_s[j]; cand_i[j + 1] = cand_i[j];
                j--;
            }
            cand_b[j + 1] = kb; cand_s[j + 1] = ks; cand_i[j + 1] = ki;
        }
        #pragma unroll
        for (int r = 0; r < TOPK; r++) {
            out[(size_t)token * TOPK + r]                         = (float)cand_i[r];
            out[(size_t)TOKENS * TOPK + (size_t)token * TOPK + r] = cand_s[r] * RSCALE;
        }
    }
}

extern "C" void kernel_launch(void* const* d_in, const int* in_sizes, int n_in,
                              void* d_out, int out_size) {
    const float* A    = (const float*)d_in[0];
    const float* W    = (const float*)d_in[1];
    const float* bias = (const float*)d_in[2];
    float* out = (float*)d_out;

    dim3 grid(EXPERTS / BN, TOKENS / BM);   // (12, 64)
    router_gemm_fp16<<<grid, 256>>>(A, W);
    topk_kernel<<<TOKENS, 256>>>(A, W, bias, out);
}

// round 7
// speedup vs baseline: 3.7217x; 1.8803x over previous
#include <cuda_runtime.h>
#include <cuda_fp16.h>
#include <math_constants.h>
#include <cstdint>

#define TOKENS  8192
#define HIDDEN  6144
#define EXPERTS 768
#define TOPK    12
#define NCAND   13
#define RSCALE  2.5f
#define TAU     1e-4f

// ---------------- GEMM config ----------------
#define BM 128
#define BN 128
#define BK 32
#define NSTAGES (HIDDEN / BK)   // 192
#define ROWB 80                 // bytes per smem row: 64B data + 16B pad (5r mod 8 distinct)
#define ATILE_B (128 * ROWB)    // 10240
#define BUF_B   (2 * ATILE_B)   // A | B

__device__ float g_logits[(size_t)TOKENS * EXPERTS];

// ---------------- helpers ----------------
__device__ __forceinline__ uint32_t smem_u32(const void* p) {
    uint32_t a;
    asm("{ .reg .u64 t; cvta.to.shared.u64 t, %1; cvt.u32.u64 %0, t; }" : "=r"(a) : "l"(p));
    return a;
}
__device__ __forceinline__ uint2 f4_to_h4(float4 v) {
    __half2 p0 = __floats2half2_rn(v.x, v.y);
    __half2 p1 = __floats2half2_rn(v.z, v.w);
    return make_uint2(*(uint32_t*)&p0, *(uint32_t*)&p1);
}
__device__ __forceinline__ void ldm_x4(uint32_t* r, uint32_t addr) {
    asm volatile("ldmatrix.sync.aligned.m8n8.x4.shared.b16 {%0,%1,%2,%3}, [%4];"
                 : "=r"(r[0]), "=r"(r[1]), "=r"(r[2]), "=r"(r[3]) : "r"(addr));
}
__device__ __forceinline__ void ldm_x2(uint32_t* r, uint32_t addr) {
    asm volatile("ldmatrix.sync.aligned.m8n8.x2.shared.b16 {%0,%1}, [%2];"
                 : "=r"(r[0]), "=r"(r[1]) : "r"(addr));
}
__device__ __forceinline__ void mma16(float* c, const uint32_t* a, const uint32_t* b) {
    asm volatile(
        "mma.sync.aligned.m16n8k16.row.col.f32.f16.f16.f32 "
        "{%0,%1,%2,%3}, {%4,%5,%6,%7}, {%8,%9}, {%0,%1,%2,%3};"
        : "+f"(c[0]), "+f"(c[1]), "+f"(c[2]), "+f"(c[3])
        : "r"(a[0]), "r"(a[1]), "r"(a[2]), "r"(a[3]), "r"(b[0]), "r"(b[1]));
}

// ---------------------------------------------------------------------------
// fp16-hi mma GEMM: logits[m][e] ~= sum_k fp16(A[m][k]) * fp16(W[e][k])
// 8 warps: 2(m) x 4(n); warp tile 64x32; per-thread 4x4 m16n8 tiles.
// ---------------------------------------------------------------------------
__global__ __launch_bounds__(256, 2)
void router_gemm_h(const float* __restrict__ A, const float* __restrict__ B) {
    __shared__ char smbuf[2][BUF_B];   // [buf][ A(10240) | B(10240) ]

    const int tid  = threadIdx.x;
    const int wid  = tid >> 5;
    const int lane = tid & 31;
    const int m0 = blockIdx.y * BM;
    const int n0 = blockIdx.x * BN;

    const int wm = wid & 1;    // 64-row band
    const int wn = wid >> 1;   // 32-col band

    // gmem->smem writer map: 1024 float4-slots per operand, 4 per thread.
    // slot_i = tid + i*256 -> row = (tid>>3) + 32*i, kq = tid&7.
    const int wrow = tid >> 3;
    const int wkq  = tid & 7;

    const float* Abase = A + (size_t)m0 * HIDDEN;
    const float* Bbase = B + (size_t)n0 * HIDDEN;

    const uint32_t smA0 = smem_u32(&smbuf[0][0]);
    const uint32_t smB0 = smA0 + ATILE_B;

    float acc[4][4][4];
    #pragma unroll
    for (int mi = 0; mi < 4; mi++)
        #pragma unroll
        for (int ni = 0; ni < 4; ni++)
            #pragma unroll
            for (int j = 0; j < 4; j++) acc[mi][ni][j] = 0.0f;

    float4 pa[4], pb[4];

    // ---- prologue: load + store stage 0 ----
    #pragma unroll
    for (int i = 0; i < 4; i++) {
        pa[i] = *(const float4*)(Abase + (size_t)(wrow + 32 * i) * HIDDEN + wkq * 4);
        pb[i] = *(const float4*)(Bbase + (size_t)(wrow + 32 * i) * HIDDEN + wkq * 4);
    }
    #pragma unroll
    for (int i = 0; i < 4; i++) {
        *(uint2*)&smbuf[0][(wrow + 32 * i) * ROWB + wkq * 8]           = f4_to_h4(pa[i]);
        *(uint2*)&smbuf[0][ATILE_B + (wrow + 32 * i) * ROWB + wkq * 8] = f4_to_h4(pb[i]);
    }
    __syncthreads();

    // ldmatrix address components
    const uint32_t a_off = (uint32_t)((wm * 64 + (lane & 7) + ((lane >> 3) & 1) * 8) * ROWB
                                      + (lane >> 4) * 16);
    const uint32_t b_off = (uint32_t)((wn * 32 + (lane & 7)) * ROWB + ((lane >> 3) & 1) * 16);

    for (int s = 0; s < NSTAGES; s++) {
        const int buf = s & 1;
        const uint32_t sA = smA0 + buf * BUF_B;
        const uint32_t sB = sA + ATILE_B;

        if (s + 1 < NSTAGES) {
            const int k0 = (s + 1) * BK;
            #pragma unroll
            for (int i = 0; i < 4; i++) {
                pa[i] = *(const float4*)(Abase + (size_t)(wrow + 32 * i) * HIDDEN + k0 + wkq * 4);
                pb[i] = *(const float4*)(Bbase + (size_t)(wrow + 32 * i) * HIDDEN + k0 + wkq * 4);
            }
        }

        #pragma unroll
        for (int w = 0; w < 2; w++) {   // two k16 windows of BK=32
            uint32_t afr[4][4], bfr[4][2];
            #pragma unroll
            for (int mi = 0; mi < 4; mi++)
                ldm_x4(afr[mi], sA + a_off + mi * (16 * ROWB) + w * 32);
            #pragma unroll
            for (int ni = 0; ni < 4; ni++)
                ldm_x2(bfr[ni], sB + b_off + ni * (8 * ROWB) + w * 32);
            #pragma unroll
            for (int mi = 0; mi < 4; mi++)
                #pragma unroll
                for (int ni = 0; ni < 4; ni++)
                    mma16(acc[mi][ni], afr[mi], bfr[ni]);
        }

        if (s + 1 < NSTAGES) {
            const int nb = buf ^ 1;
            #pragma unroll
            for (int i = 0; i < 4; i++) {
                *(uint2*)&smbuf[nb][(wrow + 32 * i) * ROWB + wkq * 8]           = f4_to_h4(pa[i]);
                *(uint2*)&smbuf[nb][ATILE_B + (wrow + 32 * i) * ROWB + wkq * 8] = f4_to_h4(pb[i]);
            }
        }
        __syncthreads();
    }

    // ---- epilogue ----
    #pragma unroll
    for (int mi = 0; mi < 4; mi++) {
        const int row = m0 + wm * 64 + mi * 16 + (lane >> 2);
        #pragma unroll
        for (int ni = 0; ni < 4; ni++) {
            const int col = n0 + wn * 32 + ni * 8 + (lane & 3) * 2;
            *(float2*)(g_logits + (size_t)row * EXPERTS + col)       = make_float2(acc[mi][ni][0], acc[mi][ni][1]);
            *(float2*)(g_logits + (size_t)(row + 8) * EXPERTS + col) = make_float2(acc[mi][ni][2], acc[mi][ni][3]);
        }
    }
}

// ---------------------------------------------------------------------------
// Softmax + top-13 candidates + exact rescore of tight pairs + sort.
// ---------------------------------------------------------------------------
__global__ __launch_bounds__(256)
void topk_kernel(const float* __restrict__ A, const float* __restrict__ W,
                 const float* __restrict__ bias, float* __restrict__ out) {
    const int token = blockIdx.x;
    const int tid   = threadIdx.x;
    const float* row = g_logits + (size_t)token * EXPERTS;

    float z[3], sc[3], bsc[3];
    #pragma unroll
    for (int i = 0; i < 3; i++) z[i] = row[tid + i * 256];

    __shared__ float red[8];
    __shared__ float wv[8];
    __shared__ int   wi[8];
    __shared__ int   s_best_i;
    __shared__ float s_m, s_inv;
    __shared__ int   cand_i[NCAND];
    __shared__ float cand_s[NCAND];
    __shared__ float cand_b[NCAND];
    __shared__ int   s_fl[NCAND];
    __shared__ int   s_nfl;

    float m = fmaxf(z[0], fmaxf(z[1], z[2]));
    #pragma unroll
    for (int off = 16; off; off >>= 1)
        m = fmaxf(m, __shfl_xor_sync(0xffffffffu, m, off));
    if ((tid & 31) == 0) red[tid >> 5] = m;
    __syncthreads();
    m = red[0];
    #pragma unroll
    for (int w = 1; w < 8; w++) m = fmaxf(m, red[w]);
    __syncthreads();

    float s = 0.0f;
    #pragma unroll
    for (int i = 0; i < 3; i++) { sc[i] = expf(z[i] - m); s += sc[i]; }
    #pragma unroll
    for (int off = 16; off; off >>= 1)
        s += __shfl_xor_sync(0xffffffffu, s, off);
    if ((tid & 31) == 0) red[tid >> 5] = s;
    __syncthreads();
    s = 0.0f;
    #pragma unroll
    for (int w = 0; w < 8; w++) s += red[w];
    const float inv = 1.0f / s;
    if (tid == 0) { s_m = m; s_inv = inv; }
    #pragma unroll
    for (int i = 0; i < 3; i++) {
        sc[i] *= inv;
        bsc[i] = sc[i] + bias[tid + i * 256];
    }

    for (int sel = 0; sel < NCAND; sel++) {
        float v  = bsc[0]; int li = 0;
        if (bsc[1] > v) { v = bsc[1]; li = 1; }
        if (bsc[2] > v) { v = bsc[2]; li = 2; }
        int idx = tid + li * 256;

        #pragma unroll
        for (int off = 16; off; off >>= 1) {
            float ov = __shfl_xor_sync(0xffffffffu, v,   off);
            int   oi = __shfl_xor_sync(0xffffffffu, idx, off);
            if (ov > v || (ov == v && oi < idx)) { v = ov; idx = oi; }
        }
        if ((tid & 31) == 0) { wv[tid >> 5] = v; wi[tid >> 5] = idx; }
        __syncthreads();

        if (tid == 0) {
            float bvv = wv[0]; int bi = wi[0];
            #pragma unroll
            for (int w = 1; w < 8; w++)
                if (wv[w] > bvv || (wv[w] == bvv && wi[w] < bi)) { bvv = wv[w]; bi = wi[w]; }
            s_best_i = bi;
        }
        __syncthreads();

        const int e = s_best_i;
        if ((e & 255) == tid) {
            const int slot = e >> 8;
            cand_i[sel] = e;
            cand_s[sel] = sc[slot];
            cand_b[sel] = bsc[slot];
            bsc[slot] = -CUDART_INF_F;
        }
        __syncthreads();
    }

    if (tid == 0) {
        int flg[NCAND];
        #pragma unroll
        for (int r = 0; r < NCAND; r++) flg[r] = 0;
        for (int r = 0; r < NCAND - 1; r++)
            if (cand_b[r] - cand_b[r + 1] < TAU) { flg[r] = 1; flg[r + 1] = 1; }
        int n = 0;
        for (int r = 0; r < NCAND; r++) if (flg[r]) s_fl[n++] = r;
        s_nfl = n;
    }
    __syncthreads();

    const int nf = s_nfl;
    const float* x = A + (size_t)token * HIDDEN;
    for (int f = 0; f < nf; f++) {
        const int slot = s_fl[f];
        const int e = cand_i[slot];
        const float* w = W + (size_t)e * HIDDEN;
        float p = 0.0f;
        #pragma unroll 8
        for (int j = tid; j < HIDDEN; j += 256)
            p = fmaf(x[j], w[j], p);
        #pragma unroll
        for (int off = 16; off; off >>= 1)
            p += __shfl_xor_sync(0xffffffffu, p, off);
        if ((tid & 31) == 0) red[tid >> 5] = p;
        __syncthreads();
        if (tid == 0) {
            float zex = 0.0f;
            #pragma unroll
            for (int w8 = 0; w8 < 8; w8++) zex += red[w8];
            float sn = expf(zex - s_m) * s_inv;
            cand_s[slot] = sn;
            cand_b[slot] = sn + bias[e];
        }
        __syncthreads();
    }

    if (tid == 0) {
        for (int i = 1; i < NCAND; i++) {
            float kb = cand_b[i], ks = cand_s[i]; int ki = cand_i[i];
            int j = i - 1;
            while (j >= 0 && (cand_b[j] < kb || (cand_b[j] == kb && cand_i[j] > ki))) {
                cand_b[j + 1] = cand_b[j]; cand_s[j + 1] = cand_s[j]; cand_i[j + 1] = cand_i[j];
                j--;
            }
            cand_b[j + 1] = kb; cand_s[j + 1] = ks; cand_i[j + 1] = ki;
        }
        #pragma unroll
        for (int r = 0; r < TOPK; r++) {
            out[(size_t)token * TOPK + r]                         = (float)cand_i[r];
            out[(size_t)TOKENS * TOPK + (size_t)token * TOPK + r] = cand_s[r] * RSCALE;
        }
    }
}

extern "C" void kernel_launch(void* const* d_in, const int* in_sizes, int n_in,
                              void* d_out, int out_size) {
    const float* A    = (const float*)d_in[0];
    const float* W    = (const float*)d_in[1];
    const float* bias = (const float*)d_in[2];
    float* out = (float*)d_out;

    dim3 grid(EXPERTS / BN, TOKENS / BM);   // (6, 64)
    router_gemm_h<<<grid, 256>>>(A, W);
    topk_kernel<<<TOKENS, 256>>>(A, W, bias, out);
}

// round 8
// speedup vs baseline: 6.4243x; 1.7261x over previous
#include <cuda_runtime.h>
#include <cuda_fp16.h>
#include <math_constants.h>
#include <cstdint>

#define TOKENS  8192
#define HIDDEN  6144
#define EXPERTS 768
#define TOPK    12
#define NCAND   13
#define RSCALE  2.5f
#define TAU     1e-4f

// ---------------- GEMM config ----------------
#define BM 128
#define BN 128
#define BK 64                    // fp16 elems per stage row = 128 B (SW128 atom)
#define NSTAGES (HIDDEN / BK)    // 96
#define RING 3
#define TILE_B  (BM * 128)       // 16384 bytes per operand stage
#define STAGE_B (2 * TILE_B)     // 32768
#define GEMM_SMEM (RING * STAGE_B)  // 98304

__device__ __half g_Ah[(size_t)TOKENS * HIDDEN];    // 96 MB
__device__ __half g_Wh[(size_t)EXPERTS * HIDDEN];   // 9 MB
__device__ float  g_logits[(size_t)TOKENS * EXPERTS];

// ---------------- helpers ----------------
__device__ __forceinline__ uint32_t smem_u32(const void* p) {
    uint32_t a;
    asm("{ .reg .u64 t; cvta.to.shared.u64 t, %1; cvt.u32.u64 %0, t; }" : "=r"(a) : "l"(p));
    return a;
}
__device__ __forceinline__ uint2 f4_to_h4(float4 v) {
    __half2 p0 = __floats2half2_rn(v.x, v.y);
    __half2 p1 = __floats2half2_rn(v.z, v.w);
    return make_uint2(*(uint32_t*)&p0, *(uint32_t*)&p1);
}
__device__ __forceinline__ void cp16(uint32_t dst, const void* src) {
    asm volatile("cp.async.cg.shared.global [%0], [%1], 16;" :: "r"(dst), "l"(src) : "memory");
}
#define CP_COMMIT() asm volatile("cp.async.commit_group;" ::: "memory")
#define CP_WAIT1()  asm volatile("cp.async.wait_group 1;" ::: "memory")

__device__ __forceinline__ void ldm_x4(uint32_t* r, uint32_t addr) {
    asm volatile("ldmatrix.sync.aligned.m8n8.x4.shared.b16 {%0,%1,%2,%3}, [%4];"
                 : "=r"(r[0]), "=r"(r[1]), "=r"(r[2]), "=r"(r[3]) : "r"(addr));
}
__device__ __forceinline__ void mma16(float* c, const uint32_t* a, const uint32_t* b) {
    asm volatile(
        "mma.sync.aligned.m16n8k16.row.col.f32.f16.f16.f32 "
        "{%0,%1,%2,%3}, {%4,%5,%6,%7}, {%8,%9}, {%0,%1,%2,%3};"
        : "+f"(c[0]), "+f"(c[1]), "+f"(c[2]), "+f"(c[3])
        : "r"(a[0]), "r"(a[1]), "r"(a[2]), "r"(a[3]), "r"(b[0]), "r"(b[1]));
}
// SW128 swizzle: 16B-chunk column XORed with row&7
__device__ __forceinline__ uint32_t swz(int row, int ch) {
    return (uint32_t)(row * 128 + ((ch ^ (row & 7)) << 4));
}

// ---------------------------------------------------------------------------
// fp32 -> fp16 conversion (grid-stride over float4)
// ---------------------------------------------------------------------------
__global__ __launch_bounds__(256)
void cvt_kernel(const float4* __restrict__ in, uint2* __restrict__ out, int n4) {
    int i = blockIdx.x * blockDim.x + threadIdx.x;
    const int stride = gridDim.x * blockDim.x;
    for (; i < n4; i += stride) out[i] = f4_to_h4(in[i]);
}

// ---------------------------------------------------------------------------
// fp16 GEMM, cp.async 3-stage ring, SW128-swizzled smem, paired ldmatrix.x4.
// 8 warps: 2(m) x 4(n); warp tile 64x32.
// ---------------------------------------------------------------------------
__global__ __launch_bounds__(256, 2)
void router_gemm_cp() {
    extern __shared__ char smem[];
    const uint32_t smbase = smem_u32(smem);

    const int tid  = threadIdx.x;
    const int wid  = tid >> 5;
    const int lane = tid & 31;
    const int m0 = blockIdx.y * BM;
    const int n0 = blockIdx.x * BN;

    const int wm = wid & 1;
    const int wn = wid >> 1;

    // cp.async writer map: 1024 16B-chunks per operand; 4 per thread.
    const int wrow = tid >> 3;    // +32*i
    const int wc   = tid & 7;

    const __half* Abase = g_Ah + (size_t)m0 * HIDDEN;
    const __half* Bbase = g_Wh + (size_t)n0 * HIDDEN;

    float acc[4][4][4];
    #pragma unroll
    for (int mi = 0; mi < 4; mi++)
        #pragma unroll
        for (int ni = 0; ni < 4; ni++)
            #pragma unroll
            for (int j = 0; j < 4; j++) acc[mi][ni][j] = 0.0f;

    // issue one stage's cp.asyncs
    auto issue = [&](int s) {
        const uint32_t slot = smbase + (s % RING) * STAGE_B;
        const __half* ga = Abase + s * BK;
        const __half* gb = Bbase + s * BK;
        #pragma unroll
        for (int i = 0; i < 4; i++) {
            const int row = wrow + 32 * i;
            const uint32_t so = swz(row, wc);
            cp16(slot + so,          ga + (size_t)row * HIDDEN + wc * 8);
            cp16(slot + TILE_B + so, gb + (size_t)row * HIDDEN + wc * 8);
        }
    };

    issue(0); CP_COMMIT();
    issue(1); CP_COMMIT();

    // ldmatrix lane-address components (row, chunk) per fragment class
    const int a_row = wm * 64 + (lane & 7) + ((lane >> 3) & 1) * 8;  // + mi*16
    const int a_chl = (lane >> 4) & 1;                                // + w*2
    const int b_row = wn * 32 + (lane & 7) + ((lane >> 4) & 1) * 8;  // + p*16
    const int b_chl = (lane >> 3) & 1;                                // + w*2

    for (int s = 0; s < NSTAGES; s++) {
        CP_WAIT1();
        __syncthreads();
        if (s + 2 < NSTAGES) issue(s + 2);
        CP_COMMIT();

        const uint32_t sA = smbase + (s % RING) * STAGE_B;
        const uint32_t sB = sA + TILE_B;

        #pragma unroll
        for (int w = 0; w < 4; w++) {       // four k16 windows of BK=64
            uint32_t af[4][4], bf[2][4];
            #pragma unroll
            for (int mi = 0; mi < 4; mi++)
                ldm_x4(af[mi], sA + swz(a_row + mi * 16, w * 2 + a_chl));
            #pragma unroll
            for (int p = 0; p < 2; p++)
                ldm_x4(bf[p], sB + swz(b_row + p * 16, w * 2 + b_chl));
            #pragma unroll
            for (int mi = 0; mi < 4; mi++) {
                mma16(acc[mi][0], af[mi], &bf[0][0]);
                mma16(acc[mi][1], af[mi], &bf[0][2]);
                mma16(acc[mi][2], af[mi], &bf[1][0]);
                mma16(acc[mi][3], af[mi], &bf[1][2]);
            }
        }
        __syncthreads();
    }

    #pragma unroll
    for (int mi = 0; mi < 4; mi++) {
        const int row = m0 + wm * 64 + mi * 16 + (lane >> 2);
        #pragma unroll
        for (int ni = 0; ni < 4; ni++) {
            const int col = n0 + wn * 32 + ni * 8 + (lane & 3) * 2;
            *(float2*)(g_logits + (size_t)row * EXPERTS + col)       = make_float2(acc[mi][ni][0], acc[mi][ni][1]);
            *(float2*)(g_logits + (size_t)(row + 8) * EXPERTS + col) = make_float2(acc[mi][ni][2], acc[mi][ni][3]);
        }
    }
}

// ---------------------------------------------------------------------------
// Warp-per-token softmax + top-13 + exact rescore of tight pairs + sort.
// 8 warps/block, no __syncthreads, everything in registers.
// ---------------------------------------------------------------------------
__global__ __launch_bounds__(256)
void topk_warp(const float* __restrict__ A, const float* __restrict__ W,
               const float* __restrict__ bias, float* __restrict__ out) {
    const int lane  = threadIdx.x & 31;
    const int token = blockIdx.x * 8 + (threadIdx.x >> 5);
    const float* row = g_logits + (size_t)token * EXPERTS;

    float sc[24], bsc[24];
    #pragma unroll
    for (int j = 0; j < 24; j++) sc[j] = row[j * 32 + lane];

    // softmax
    float m = sc[0];
    #pragma unroll
    for (int j = 1; j < 24; j++) m = fmaxf(m, sc[j]);
    #pragma unroll
    for (int off = 16; off; off >>= 1) m = fmaxf(m, __shfl_xor_sync(0xffffffffu, m, off));
    float ssum = 0.0f;
    #pragma unroll
    for (int j = 0; j < 24; j++) { sc[j] = expf(sc[j] - m); ssum += sc[j]; }
    #pragma unroll
    for (int off = 16; off; off >>= 1) ssum += __shfl_xor_sync(0xffffffffu, ssum, off);
    const float inv = 1.0f / ssum;
    #pragma unroll
    for (int j = 0; j < 24; j++) {
        sc[j] *= inv;
        bsc[j] = sc[j] + bias[j * 32 + lane];
    }

    float cb[NCAND], cs[NCAND];
    int   ce[NCAND];

    // 13 selection rounds (tie -> lower expert index, matching lax.top_k)
    #pragma unroll
    for (int sel = 0; sel < NCAND; sel++) {
        float v = bsc[0]; int je = 0;
        #pragma unroll
        for (int j = 1; j < 24; j++) if (bsc[j] > v) { v = bsc[j]; je = j; }
        int idx = je * 32 + lane;
        #pragma unroll
        for (int off = 16; off; off >>= 1) {
            float ov = __shfl_xor_sync(0xffffffffu, v,   off);
            int   oi = __shfl_xor_sync(0xffffffffu, idx, off);
            if (ov > v || (ov == v && oi < idx)) { v = ov; idx = oi; }
        }
        float mysc = 0.0f;
        if ((idx & 31) == lane) {
            const int jw = idx >> 5;
            #pragma unroll
            for (int j = 0; j < 24; j++)
                if (j == jw) { mysc = sc[j]; bsc[j] = -CUDART_INF_F; }
        }
        const float wsc = __shfl_sync(0xffffffffu, mysc, idx & 31);
        cb[sel] = v; cs[sel] = wsc; ce[sel] = idx;
    }

    // flag tight adjacent pairs (warp-uniform)
    bool fl[NCAND];
    #pragma unroll
    for (int r = 0; r < NCAND; r++) fl[r] = false;
    #pragma unroll
    for (int r = 0; r < NCAND - 1; r++)
        if (cb[r] - cb[r + 1] < TAU) { fl[r] = true; fl[r + 1] = true; }

    // exact fp32 rescore of flagged candidates (warp-cooperative dot)
    const float* x = A + (size_t)token * HIDDEN;
    #pragma unroll
    for (int r = 0; r < NCAND; r++) {
        if (fl[r]) {
            const float* w = W + (size_t)ce[r] * HIDDEN;
            float p = 0.0f;
            #pragma unroll 8
            for (int jj = lane; jj < HIDDEN; jj += 32)
                p = fmaf(x[jj], w[jj], p);
            #pragma unroll
            for (int off = 16; off; off >>= 1)
                p += __shfl_xor_sync(0xffffffffu, p, off);
            const float sn = expf(p - m) * inv;
            cs[r] = sn;
            cb[r] = sn + bias[ce[r]];
        }
    }

    // unrolled bubble sort (desc cb, tie -> lower index); static indices -> regs
    #pragma unroll
    for (int i = 0; i < NCAND - 1; i++)
        #pragma unroll
        for (int j = 0; j < NCAND - 1 - i; j++) {
            const bool sw = (cb[j] < cb[j + 1]) ||
                            (cb[j] == cb[j + 1] && ce[j] > ce[j + 1]);
            if (sw) {
                float tb = cb[j]; cb[j] = cb[j + 1]; cb[j + 1] = tb;
                float ts = cs[j]; cs[j] = cs[j + 1]; cs[j + 1] = ts;
                int   te = ce[j]; ce[j] = ce[j + 1]; ce[j + 1] = te;
            }
        }

    if (lane == 0) {
        #pragma unroll
        for (int r = 0; r < TOPK; r++) {
            out[(size_t)token * TOPK + r]                         = (float)ce[r];
            out[(size_t)TOKENS * TOPK + (size_t)token * TOPK + r] = cs[r] * RSCALE;
        }
    }
}

extern "C" void kernel_launch(void* const* d_in, const int* in_sizes, int n_in,
                              void* d_out, int out_size) {
    const float* A    = (const float*)d_in[0];
    const float* W    = (const float*)d_in[1];
    const float* bias = (const float*)d_in[2];
    float* out = (float*)d_out;

    __half* dAh = nullptr; __half* dWh = nullptr;
    cudaGetSymbolAddress((void**)&dAh, g_Ah);
    cudaGetSymbolAddress((void**)&dWh, g_Wh);

    cvt_kernel<<<2048, 256>>>((const float4*)A, (uint2*)dAh, TOKENS * HIDDEN / 4);
    cvt_kernel<<<256, 256>>>((const float4*)W, (uint2*)dWh, EXPERTS * HIDDEN / 4);

    cudaFuncSetAttribute(router_gemm_cp, cudaFuncAttributeMaxDynamicSharedMemorySize, GEMM_SMEM);
    dim3 grid(EXPERTS / BN, TOKENS / BM);   // (6, 64)
    router_gemm_cp<<<grid, 256, GEMM_SMEM>>>();

    topk_warp<<<TOKENS / 8, 256>>>(A, W, bias, out);
}

// round 9
// speedup vs baseline: 7.1518x; 1.1132x over previous
#include <cuda_runtime.h>
#include <cuda_fp16.h>
#include <math_constants.h>
#include <cstdint>

#define TOKENS  8192
#define HIDDEN  6144
#define EXPERTS 768
#define TOPK    12
#define NCAND   13
#define RSCALE  2.5f
#define TAU     1e-4f

// ---------------- GEMM config ----------------
#define BM 128
#define BN 128
#define BK 64                    // fp16 elems per stage row = 128 B (SW128 atom)
#define NSTAGES (HIDDEN / BK)    // 96
#define RING 3
#define TILE_B  (BM * 128)       // 16384 bytes per operand stage
#define STAGE_B (2 * TILE_B)     // 32768
#define GEMM_SMEM (RING * STAGE_B)  // 98304

__device__ __half g_Ah[(size_t)TOKENS * HIDDEN];    // 96 MB
__device__ __half g_Wh[(size_t)EXPERTS * HIDDEN];   // 9 MB
__device__ float  g_logits[(size_t)TOKENS * EXPERTS];

// ---------------- helpers ----------------
__device__ __forceinline__ uint32_t smem_u32(const void* p) {
    uint32_t a;
    asm("{ .reg .u64 t; cvta.to.shared.u64 t, %1; cvt.u32.u64 %0, t; }" : "=r"(a) : "l"(p));
    return a;
}
__device__ __forceinline__ uint2 f4_to_h4(float4 v) {
    __half2 p0 = __floats2half2_rn(v.x, v.y);
    __half2 p1 = __floats2half2_rn(v.z, v.w);
    return make_uint2(*(uint32_t*)&p0, *(uint32_t*)&p1);
}
__device__ __forceinline__ void cp16(uint32_t dst, const void* src) {
    asm volatile("cp.async.cg.shared.global [%0], [%1], 16;" :: "r"(dst), "l"(src) : "memory");
}
#define CP_COMMIT() asm volatile("cp.async.commit_group;" ::: "memory")
#define CP_WAIT1()  asm volatile("cp.async.wait_group 1;" ::: "memory")

__device__ __forceinline__ void ldm_x4(uint32_t* r, uint32_t addr) {
    asm volatile("ldmatrix.sync.aligned.m8n8.x4.shared.b16 {%0,%1,%2,%3}, [%4];"
                 : "=r"(r[0]), "=r"(r[1]), "=r"(r[2]), "=r"(r[3]) : "r"(addr));
}
__device__ __forceinline__ void mma16(float* c, const uint32_t* a, const uint32_t* b) {
    asm volatile(
        "mma.sync.aligned.m16n8k16.row.col.f32.f16.f16.f32 "
        "{%0,%1,%2,%3}, {%4,%5,%6,%7}, {%8,%9}, {%0,%1,%2,%3};"
        : "+f"(c[0]), "+f"(c[1]), "+f"(c[2]), "+f"(c[3])
        : "r"(a[0]), "r"(a[1]), "r"(a[2]), "r"(a[3]), "r"(b[0]), "r"(b[1]));
}
__device__ __forceinline__ uint32_t swz(int row, int ch) {
    return (uint32_t)(row * 128 + ((ch ^ (row & 7)) << 4));
}

// ---------------------------------------------------------------------------
// fp32 -> fp16 conversion (grid-stride over float4)
// ---------------------------------------------------------------------------
__global__ __launch_bounds__(256)
void cvt_kernel(const float4* __restrict__ in, uint2* __restrict__ out, int n4) {
    int i = blockIdx.x * blockDim.x + threadIdx.x;
    const int stride = gridDim.x * blockDim.x;
    for (; i < n4; i += stride) out[i] = f4_to_h4(in[i]);
}

// ---------------------------------------------------------------------------
// fp16 GEMM, cp.async 3-stage ring, SW128-swizzled smem (unchanged from R8).
// ---------------------------------------------------------------------------
__global__ __launch_bounds__(256, 2)
void router_gemm_cp() {
    extern __shared__ char smem[];
    const uint32_t smbase = smem_u32(smem);

    const int tid  = threadIdx.x;
    const int wid  = tid >> 5;
    const int lane = tid & 31;
    const int m0 = blockIdx.y * BM;
    const int n0 = blockIdx.x * BN;

    const int wm = wid & 1;
    const int wn = wid >> 1;

    const int wrow = tid >> 3;
    const int wc   = tid & 7;

    const __half* Abase = g_Ah + (size_t)m0 * HIDDEN;
    const __half* Bbase = g_Wh + (size_t)n0 * HIDDEN;

    float acc[4][4][4];
    #pragma unroll
    for (int mi = 0; mi < 4; mi++)
        #pragma unroll
        for (int ni = 0; ni < 4; ni++)
            #pragma unroll
            for (int j = 0; j < 4; j++) acc[mi][ni][j] = 0.0f;

    auto issue = [&](int s) {
        const uint32_t slot = smbase + (s % RING) * STAGE_B;
        const __half* ga = Abase + s * BK;
        const __half* gb = Bbase + s * BK;
        #pragma unroll
        for (int i = 0; i < 4; i++) {
            const int row = wrow + 32 * i;
            const uint32_t so = swz(row, wc);
            cp16(slot + so,          ga + (size_t)row * HIDDEN + wc * 8);
            cp16(slot + TILE_B + so, gb + (size_t)row * HIDDEN + wc * 8);
        }
    };

    issue(0); CP_COMMIT();
    issue(1); CP_COMMIT();

    const int a_row = wm * 64 + (lane & 7) + ((lane >> 3) & 1) * 8;
    const int a_chl = (lane >> 4) & 1;
    const int b_row = wn * 32 + (lane & 7) + ((lane >> 4) & 1) * 8;
    const int b_chl = (lane >> 3) & 1;

    for (int s = 0; s < NSTAGES; s++) {
        CP_WAIT1();
        __syncthreads();
        if (s + 2 < NSTAGES) issue(s + 2);
        CP_COMMIT();

        const uint32_t sA = smbase + (s % RING) * STAGE_B;
        const uint32_t sB = sA + TILE_B;

        #pragma unroll
        for (int w = 0; w < 4; w++) {
            uint32_t af[4][4], bf[2][4];
            #pragma unroll
            for (int mi = 0; mi < 4; mi++)
                ldm_x4(af[mi], sA + swz(a_row + mi * 16, w * 2 + a_chl));
            #pragma unroll
            for (int p = 0; p < 2; p++)
                ldm_x4(bf[p], sB + swz(b_row + p * 16, w * 2 + b_chl));
            #pragma unroll
            for (int mi = 0; mi < 4; mi++) {
                mma16(acc[mi][0], af[mi], &bf[0][0]);
                mma16(acc[mi][1], af[mi], &bf[0][2]);
                mma16(acc[mi][2], af[mi], &bf[1][0]);
                mma16(acc[mi][3], af[mi], &bf[1][2]);
            }
        }
        __syncthreads();
    }

    #pragma unroll
    for (int mi = 0; mi < 4; mi++) {
        const int row = m0 + wm * 64 + mi * 16 + (lane >> 2);
        #pragma unroll
        for (int ni = 0; ni < 4; ni++) {
            const int col = n0 + wn * 32 + ni * 8 + (lane & 3) * 2;
            *(float2*)(g_logits + (size_t)row * EXPERTS + col)       = make_float2(acc[mi][ni][0], acc[mi][ni][1]);
            *(float2*)(g_logits + (size_t)(row + 8) * EXPERTS + col) = make_float2(acc[mi][ni][2], acc[mi][ni][3]);
        }
    }
}

// ---------------------------------------------------------------------------
// Warp-per-token topk, low-register edition:
//  - only biased scores kept in registers (24 regs)
//  - candidate lists in per-warp smem (warp-uniform values, lane-0 stores)
//  - winner's unbiased score recovered as v - bias[idx]
//  - rank-based parallel output (lane r ranks candidate r)
// ---------------------------------------------------------------------------
__global__ __launch_bounds__(256, 4)
void topk_warp(const float* __restrict__ A, const float* __restrict__ W,
               const float* __restrict__ bias, float* __restrict__ out) {
    const int lane  = threadIdx.x & 31;
    const int wslot = threadIdx.x >> 5;
    const int token = blockIdx.x * 8 + wslot;
    const float* row = g_logits + (size_t)token * EXPERTS;

    __shared__ float s_cb[8][NCAND];
    __shared__ float s_cs[8][NCAND];
    __shared__ int   s_ce[8][NCAND];

    float b[24];
    #pragma unroll
    for (int j = 0; j < 24; j++) b[j] = row[j * 32 + lane];

    // softmax stats
    float m = b[0];
    #pragma unroll
    for (int j = 1; j < 24; j++) m = fmaxf(m, b[j]);
    #pragma unroll
    for (int off = 16; off; off >>= 1) m = fmaxf(m, __shfl_xor_sync(0xffffffffu, m, off));
    float ssum = 0.0f;
    #pragma unroll
    for (int j = 0; j < 24; j++) { b[j] = expf(b[j] - m); ssum += b[j]; }
    #pragma unroll
    for (int off = 16; off; off >>= 1) ssum += __shfl_xor_sync(0xffffffffu, ssum, off);
    const float inv = 1.0f / ssum;
    // b[] becomes biased score
    #pragma unroll
    for (int j = 0; j < 24; j++) b[j] = fmaf(b[j], inv, __ldg(&bias[j * 32 + lane]));

    // 13 selection rounds (tie -> lower expert index)
    for (int sel = 0; sel < NCAND; sel++) {
        float v = b[0]; int je = 0;
        #pragma unroll
        for (int j = 1; j < 24; j++) if (b[j] > v) { v = b[j]; je = j; }
        int idx = je * 32 + lane;
        #pragma unroll
        for (int off = 16; off; off >>= 1) {
            float ov = __shfl_xor_sync(0xffffffffu, v,   off);
            int   oi = __shfl_xor_sync(0xffffffffu, idx, off);
            if (ov > v || (ov == v && oi < idx)) { v = ov; idx = oi; }
        }
        if ((idx & 31) == lane) {
            const int jw = idx >> 5;
            #pragma unroll
            for (int j = 0; j < 24; j++) if (j == jw) b[j] = -CUDART_INF_F;
        }
        if (lane == 0) {
            s_cb[wslot][sel] = v;
            s_cs[wslot][sel] = v - __ldg(&bias[idx]);  // unbiased score recovery
            s_ce[wslot][sel] = idx;
        }
    }
    __syncwarp();

    // flag mask from ORIGINAL approx scores (warp-uniform)
    unsigned fmask = 0;
    #pragma unroll
    for (int r = 0; r < NCAND - 1; r++)
        if (s_cb[wslot][r] - s_cb[wslot][r + 1] < TAU) fmask |= (3u << r);

    // exact fp32 rescore of flagged candidates
    const float* x = A + (size_t)token * HIDDEN;
    while (fmask) {
        const int r = __ffs(fmask) - 1;
        fmask &= fmask - 1;
        const int e = s_ce[wslot][r];
        const float* w = W + (size_t)e * HIDDEN;
        float p = 0.0f;
        #pragma unroll 8
        for (int jj = lane; jj < HIDDEN; jj += 32)
            p = fmaf(x[jj], w[jj], p);
        #pragma unroll
        for (int off = 16; off; off >>= 1)
            p += __shfl_xor_sync(0xffffffffu, p, off);
        if (lane == 0) {
            const float sn = expf(p - m) * inv;
            s_cs[wslot][r] = sn;
            s_cb[wslot][r] = sn + __ldg(&bias[e]);
        }
    }
    __syncwarp();

    // rank-based parallel output: lane r (<13) ranks its candidate
    if (lane < NCAND) {
        const float mv = s_cb[wslot][lane];
        const int   me = s_ce[wslot][lane];
        int rank = 0;
        #pragma unroll
        for (int j = 0; j < NCAND; j++) {
            const float jv = s_cb[wslot][j];
            const int   jee = s_ce[wslot][j];
            if (jv > mv || (jv == mv && jee < me)) rank++;
        }
        if (rank < TOPK) {
            out[(size_t)token * TOPK + rank]                         = (float)me;
            out[(size_t)TOKENS * TOPK + (size_t)token * TOPK + rank] = s_cs[wslot][lane] * RSCALE;
        }
    }
}

extern "C" void kernel_launch(void* const* d_in, const int* in_sizes, int n_in,
                              void* d_out, int out_size) {
    const float* A    = (const float*)d_in[0];
    const float* W    = (const float*)d_in[1];
    const float* bias = (const float*)d_in[2];
    float* out = (float*)d_out;

    __half* dAh = nullptr; __half* dWh = nullptr;
    cudaGetSymbolAddress((void**)&dAh, g_Ah);
    cudaGetSymbolAddress((void**)&dWh, g_Wh);

    cvt_kernel<<<2048, 256>>>((const float4*)A, (uint2*)dAh, TOKENS * HIDDEN / 4);
    cvt_kernel<<<256, 256>>>((const float4*)W, (uint2*)dWh, EXPERTS * HIDDEN / 4);

    cudaFuncSetAttribute(router_gemm_cp, cudaFuncAttributeMaxDynamicSharedMemorySize, GEMM_SMEM);
    dim3 grid(EXPERTS / BN, TOKENS / BM);   // (6, 64)
    router_gemm_cp<<<grid, 256, GEMM_SMEM>>>();

    topk_warp<<<TOKENS / 8, 256>>>(A, W, bias, out);
}